// round 4
// baseline (speedup 1.0000x reference)
#include <cuda_runtime.h>
#include <math.h>

// ---------------- problem constants ----------------
#define S      31
#define HW     (S*S)          // 961
#define B      256
#define HDC    4096
#define RBF    5
#define MODES  16
#define STEPS  8
#define NROWS  (RBF*5*HW)     // 24025 reduction rows of 4096 floats
#define NSLOTS (5*HDC)        // 20480 scatter slots (batch 0 only)
#define ROWBLK ((NROWS*32 + 255)/256)   // blocks doing row reductions (warp/row)

// padded NCA tile: 33x33 per channel
#define PS  33
#define PHW (PS*PS)           // 1089

// ---------------- device scratch (no allocation; zero-initialized) --------
__device__ float g_mp [NROWS];
__device__ float g_mp2[NROWS];
__device__ int   g_pack[NSLOTS];   // 0 = empty; else ((i+1)<<1)|sign
__device__ float g_out0[5*HW];
__device__ float g_outg[5*HW];

// ====== Kernel A: probe mean/mean-sq (warp per row) + fused scatter =======
__global__ __launch_bounds__(256)
void probe_scatter_kernel(const float* __restrict__ probes,
                          const int*   __restrict__ nzi,
                          const int*   __restrict__ signs, int nnz)
{
    if (blockIdx.x >= ROWBLK) {
        // ---- scatter part: last-write-wins packed atomicMax ----
        int i = (blockIdx.x - ROWBLK) * 256 + threadIdx.x;
        if (i < nnz) {
            int slot = nzi[i];
            if (slot >= 0 && slot < NSLOTS) {
                int packed = ((i + 1) << 1) | (signs[i] & 1);
                atomicMax(&g_pack[slot], packed);
            }
        }
        return;
    }

    const int gwarp = (blockIdx.x * 256 + threadIdx.x) >> 5;
    const int lane  = threadIdx.x & 31;
    if (gwarp >= NROWS) return;

    const float4* __restrict__ p =
        reinterpret_cast<const float4*>(probes) + (size_t)gwarp * 1024;

    float s = 0.f, s2 = 0.f;
#pragma unroll
    for (int i = 0; i < 32; i++) {
        float4 v = p[lane + i * 32];
        s  += (v.x + v.y) + (v.z + v.w);
        s2 += (v.x*v.x + v.y*v.y) + (v.z*v.z + v.w*v.w);
    }
#pragma unroll
    for (int o = 16; o; o >>= 1) {
        s  += __shfl_down_sync(0xffffffffu, s,  o);
        s2 += __shfl_down_sync(0xffffffffu, s2, o);
    }
    if (lane == 0) {
        g_mp [gwarp] = s  * (1.f / 4096.f);
        g_mp2[gwarp] = s2 * (1.f / 4096.f);
    }
}

// ====== Kernel B: chansum + te + RBF + 8-step NCA (padded tiles) + conv ===
// blockIdx.x == 0 : batch-0 state (does chansum/te/dataSum prep too)
// blockIdx.x == 1 : generic state (proj = 0)
__global__ __launch_bounds__(1024, 1)
void nca_kernel(const float* __restrict__ din,      // (B,124,31), batch 0
                const float* __restrict__ sin_in,   // (B,31,31),  batch 0
                const float* __restrict__ t_in_arr,
                const float* __restrict__ t_out_arr,
                const float* __restrict__ ctw,      // (5,16)
                const float* __restrict__ ctb,      // (5,)
                const float* __restrict__ c3w,      // (5,)
                const float* __restrict__ c3b,      // scalar
                const float* __restrict__ ncaw,     // (5,5,3,3)
                const float* __restrict__ ncab,     // (5,)
                const float* __restrict__ spike,    // (8,)
                const float* __restrict__ outw,     // (5,5)
                const float* __restrict__ outb)     // (5,)
{
    __shared__ float hA[5 * PHW];
    __shared__ float hB[5 * PHW];
    __shared__ float sDS[HW];
    __shared__ float w9[225], bb[5], sp[8], ow[25], ob[5], c3[5];
    __shared__ float sHdc[5];
    __shared__ float ste[5];
    __shared__ float c3bS;
    __shared__ float red[32];

    const int  tid  = threadIdx.x;            // 1024
    const int  lane = tid & 31, wid = tid >> 5;
    const bool gen  = (blockIdx.x == 1);

    if (tid < 225) w9[tid] = ncaw[tid];
    if (tid < 25)  ow[tid] = outw[tid];
    if (tid < 8)   sp[tid] = spike[tid];
    if (tid < 5) { bb[tid] = ncab[tid]; ob[tid] = outb[tid]; c3[tid] = c3w[tid]; }
    if (tid == 0) c3bS = c3b[0];

    // zero both padded tiles (borders must be 0 and stay 0)
    for (int i = tid; i < 5 * PHW; i += 1024) { hA[i] = 0.f; hB[i] = 0.f; }

    if (!gen) {
        // ---- per-channel sign sums from packed scatter array (+ reset) ----
        float loc[5] = {0.f, 0.f, 0.f, 0.f, 0.f};
#pragma unroll
        for (int ch = 0; ch < 5; ch++) {
            for (int sl = ch * HDC + tid; sl < (ch + 1) * HDC; sl += 1024) {
                int v = g_pack[sl];
                if (v) {
                    g_pack[sl] = 0;                       // self-clean for replay
                    loc[ch] += (float)((v & 1) * 2 - 1);
                }
            }
        }
#pragma unroll
        for (int ch = 0; ch < 5; ch++) {
            float a = loc[ch];
#pragma unroll
            for (int o = 16; o; o >>= 1) a += __shfl_down_sync(0xffffffffu, a, o);
            if (lane == 0) red[wid] = a;
            __syncthreads();
            if (tid == 0) {
                float t = 0.f;
#pragma unroll
                for (int k = 0; k < 32; k++) t += red[k];
                sHdc[ch] = t;
            }
            __syncthreads();
        }

        // ---- time encoding (thread 0) ----
        if (tid == 0) {
            float tin  = t_in_arr[0]  * 0.01f;
            float tout = t_out_arr[0] * 0.01f;
            float pe[MODES];
#pragma unroll
            for (int i = 0; i < MODES; i++) {
                float div  = powf(10000.0f, 2.0f * (float)(i / 2) / (float)MODES);
                pe[i] = (i % 2 == 0) ? 0.5f * (sinf(tin / div) + cosf(tin / div))
                                     : 0.5f * (cosf(tin / div) + sinf(tout / div));
            }
#pragma unroll
            for (int r = 0; r < 5; r++) {
                float a = ctb[r];
#pragma unroll
                for (int m = 0; m < MODES; m++) a += pe[m] * ctw[r * MODES + m];
                ste[r] = tanhf(a);
            }
        }
        __syncthreads();

        // ---- dataSum[p] = sum_c data0[c,h,w] * (1 + te[c]) ----
        for (int p = tid; p < HW; p += 1024) {
            int h = p / S, w = p % S;
            float acc = 0.f;
#pragma unroll
            for (int c = 0; c < 4; c++)
                acc += din[(size_t)(c * S + h) * S + w] * (1.0f + ste[c]);
            acc += sin_in[p] * (1.0f + ste[4]);
            sDS[p] = acc;
        }
    }
    __syncthreads();

    const float csum = c3[0] + c3[1] + c3[2] + c3[3] + c3[4];

    // per-thread work items: up to 5 of the 4805 elements
    int n_my = 0;
    int mc[5], mh[5], mw[5];
#pragma unroll
    for (int k = 0; k < 5; k++) {
        int i = tid + k * 1024;
        if (i < 5 * HW) {
            mc[k] = i / HW;
            int p = i - mc[k] * HW;
            mh[k] = p / S; mw[k] = p - mh[k] * S;
            n_my = k + 1;
        }
    }

    // x = tanh( sum_r c3[r]*(mp2 - 2*proj*mp + proj^2) + c3b ) into padded hA
#pragma unroll
    for (int k = 0; k < 5; k++) {
        if (k >= n_my) break;
        int d = mc[k], p = mh[k] * S + mw[k];
        float a = 0.f, bm = 0.f;
#pragma unroll
        for (int r = 0; r < 5; r++) {
            int ri = (r * 5 + d) * HW + p;
            a  += c3[r] * g_mp2[ri];
            bm += c3[r] * g_mp [ri];
        }
        float proj = gen ? 0.f : (sHdc[d] * sDS[p]);
        hA[d * PHW + (mh[k] + 1) * PS + (mw[k] + 1)] =
            tanhf(a - 2.f * proj * bm + proj * proj * csum + c3bS);
    }
    __syncthreads();

    float* cur = hA;
    float* nxt = hB;
#pragma unroll
    for (int st = 0; st < STEPS; st++) {
        float ps = sp[st];
#pragma unroll
        for (int k = 0; k < 5; k++) {
            if (k >= n_my) break;
            int c = mc[k], h = mh[k], w = mw[k];
            float y = bb[c];
            const float* wr0 = w9 + c * 45;
#pragma unroll
            for (int ci = 0; ci < 5; ci++) {
                const float* base = cur + ci * PHW + h * PS + w;  // window TL
                const float* wr   = wr0 + ci * 9;
                y += wr[0]*base[0]      + wr[1]*base[1]      + wr[2]*base[2]
                   + wr[3]*base[PS]     + wr[4]*base[PS+1]   + wr[5]*base[PS+2]
                   + wr[6]*base[2*PS]   + wr[7]*base[2*PS+1] + wr[8]*base[2*PS+2];
            }
            int pos = c * PHW + (h + 1) * PS + (w + 1);
            nxt[pos] = cur[pos] + tanhf(y) * ps;
        }
        __syncthreads();
        float* t = cur; cur = nxt; nxt = t;
    }

    // out conv: (5->5) 1x1
    float* dst = gen ? g_outg : g_out0;
#pragma unroll
    for (int k = 0; k < 5; k++) {
        if (k >= n_my) break;
        int o = mc[k], h = mh[k], w = mw[k];
        int pp = (h + 1) * PS + (w + 1);
        float v0 = cur[0*PHW + pp], v1 = cur[1*PHW + pp], v2 = cur[2*PHW + pp],
              v3 = cur[3*PHW + pp], v4 = cur[4*PHW + pp];
        float acc = ob[o] + ow[o*5+0]*v0 + ow[o*5+1]*v1 + ow[o*5+2]*v2
                          + ow[o*5+3]*v3 + ow[o*5+4]*v4;
        dst[o * HW + h * S + w] = acc;
    }
}

// ====== Kernel C: broadcast — one block per (o,b) slice, coalesced =========
__global__ __launch_bounds__(256)
void writeout_kernel(float* __restrict__ out)
{
    const int s = blockIdx.x;          // s = o*B + b
    const int b = s & (B - 1);
    const int o = s >> 8;              // B == 256
    const float* __restrict__ src = ((b == 0) ? g_out0 : g_outg) + o * HW;
    float* __restrict__ dst = out + (size_t)s * HW;
#pragma unroll
    for (int k = 0; k < 4; k++) {
        int p = threadIdx.x + k * 256;
        if (p < HW) dst[p] = src[p];
    }
}

// =================================== launch ================================
extern "C" void kernel_launch(void* const* d_in, const int* in_sizes, int n_in,
                              void* d_out, int out_size)
{
    const float* data_input  = (const float*)d_in[0];
    const float* structure   = (const float*)d_in[1];
    const float* meta_in     = (const float*)d_in[2];
    const float* meta_out    = (const float*)d_in[3];
    const float* spiking     = (const float*)d_in[4];
    const int*   nz_indices  = (const int*)  d_in[5];
    const int*   signs_raw   = (const int*)  d_in[6];
    const float* rbf_probes  = (const float*)d_in[7];
    const float* ct_w        = (const float*)d_in[8];
    const float* ct_b        = (const float*)d_in[9];
    const float* c3_w        = (const float*)d_in[10];
    const float* c3_b        = (const float*)d_in[11];
    const float* nca_w       = (const float*)d_in[12];
    const float* nca_b       = (const float*)d_in[13];
    const float* out_w       = (const float*)d_in[14];
    const float* out_b       = (const float*)d_in[15];
    float* out = (float*)d_out;

    const int nnz = in_sizes[5];
    const int nblk = ROWBLK + (nnz + 255) / 256;

    probe_scatter_kernel<<<nblk, 256>>>(rbf_probes, nz_indices, signs_raw, nnz);

    nca_kernel<<<2, 1024>>>(data_input, structure, meta_in, meta_out,
                            ct_w, ct_b, c3_w, c3_b, nca_w, nca_b,
                            spiking, out_w, out_b);

    writeout_kernel<<<5 * B, 256>>>(out);
}

// round 5
// speedup vs baseline: 1.5038x; 1.5038x over previous
#include <cuda_runtime.h>
#include <math.h>

// ---------------- problem constants ----------------
#define S      31
#define HW     (S*S)          // 961
#define B      256
#define HDC    4096
#define RBF    5
#define MODES  16
#define STEPS  8
#define NROWS  (RBF*5*HW)     // 24025 reduction rows of 4096 floats
#define NSLOTS (5*HDC)        // 20480 scatter slots (batch 0 only)
#define ROWBLK ((NROWS*32 + 255)/256)   // blocks doing row reductions (warp/row)

// padded NCA tile: 33x33 per channel (row 0 / col 0 / row 32 / col 32 = zero border)
#define PS  33
#define PHW (PS*PS)           // 1089

// ---------------- device scratch (no allocation; zero-initialized) --------
__device__ float g_mp [NROWS];
__device__ float g_mp2[NROWS];
__device__ int   g_pack[NSLOTS];   // 0 = empty; else ((i+1)<<1)|sign
__device__ float g_out0[5*HW];
__device__ float g_outg[5*HW];

__device__ __forceinline__ float fast_tanh(float x)
{
    float cx = fminf(fmaxf(x, -15.f), 15.f);
    float e  = __expf(2.f * cx);
    return __fdividef(e - 1.f, e + 1.f);
}

// ====== Kernel A: probe mean/mean-sq (warp per row) + fused scatter =======
__global__ __launch_bounds__(256)
void probe_scatter_kernel(const float* __restrict__ probes,
                          const int*   __restrict__ nzi,
                          const int*   __restrict__ signs, int nnz)
{
    if (blockIdx.x >= ROWBLK) {
        int i = (blockIdx.x - ROWBLK) * 256 + threadIdx.x;
        if (i < nnz) {
            int slot = nzi[i];
            if (slot >= 0 && slot < NSLOTS) {
                int packed = ((i + 1) << 1) | (signs[i] & 1);
                atomicMax(&g_pack[slot], packed);
            }
        }
        return;
    }

    const int gwarp = (blockIdx.x * 256 + threadIdx.x) >> 5;
    const int lane  = threadIdx.x & 31;
    if (gwarp >= NROWS) return;

    const float4* __restrict__ p =
        reinterpret_cast<const float4*>(probes) + (size_t)gwarp * 1024;

    float s = 0.f, s2 = 0.f;
#pragma unroll
    for (int i = 0; i < 32; i++) {
        float4 v = p[lane + i * 32];
        s  += (v.x + v.y) + (v.z + v.w);
        s2 += (v.x*v.x + v.y*v.y) + (v.z*v.z + v.w*v.w);
    }
#pragma unroll
    for (int o = 16; o; o >>= 1) {
        s  += __shfl_down_sync(0xffffffffu, s,  o);
        s2 += __shfl_down_sync(0xffffffffu, s2, o);
    }
    if (lane == 0) {
        g_mp [gwarp] = s  * (1.f / 4096.f);
        g_mp2[gwarp] = s2 * (1.f / 4096.f);
    }
}

// ====== Kernel B: chansum + te + RBF + 8-step NCA + out conv ==============
// blockIdx.x == 0 : batch-0 state (does chansum/te/dataSum prep too)
// blockIdx.x == 1 : generic state (proj = 0)
__global__ __launch_bounds__(1024, 1)
void nca_kernel(const float* __restrict__ din,      // (B,124,31), batch 0
                const float* __restrict__ sin_in,   // (B,31,31),  batch 0
                const float* __restrict__ t_in_arr,
                const float* __restrict__ t_out_arr,
                const float* __restrict__ ctw,      // (5,16)
                const float* __restrict__ ctb,      // (5,)
                const float* __restrict__ c3w,      // (5,)
                const float* __restrict__ c3b,      // scalar
                const float* __restrict__ ncaw,     // (5,5,3,3)
                const float* __restrict__ ncab,     // (5,)
                const float* __restrict__ spike,    // (8,)
                const float* __restrict__ outw,     // (5,5)
                const float* __restrict__ outb)     // (5,)
{
    __shared__ float hA[5 * PHW];
    __shared__ float hB[5 * PHW];
    __shared__ float sDS[HW];
    __shared__ float w9[225], bb[5], sp[8], ow[25], ob[5], c3[5];
    __shared__ float sHdc[5];
    __shared__ float ste[5];
    __shared__ float c3bS;
    __shared__ float red[32];

    const int  tid  = threadIdx.x;            // 1024
    const int  lane = tid & 31, wid = tid >> 5;
    const bool gen  = (blockIdx.x == 1);

    if (tid < 225) w9[tid] = ncaw[tid];
    if (tid < 25)  ow[tid] = outw[tid];
    if (tid < 8)   sp[tid] = spike[tid];
    if (tid < 5) { bb[tid] = ncab[tid]; ob[tid] = outb[tid]; c3[tid] = c3w[tid]; }
    if (tid == 0) c3bS = c3b[0];

    // zero both padded tiles (borders must be 0 and stay 0)
    for (int i = tid; i < 5 * PHW; i += 1024) { hA[i] = 0.f; hB[i] = 0.f; }

    if (!gen) {
        // ---- per-channel sign sums from packed scatter array (+ reset) ----
        float loc[5] = {0.f, 0.f, 0.f, 0.f, 0.f};
#pragma unroll
        for (int ch = 0; ch < 5; ch++) {
            for (int sl = ch * HDC + tid; sl < (ch + 1) * HDC; sl += 1024) {
                int v = g_pack[sl];
                if (v) {
                    g_pack[sl] = 0;                       // self-clean for replay
                    loc[ch] += (float)((v & 1) * 2 - 1);
                }
            }
        }
#pragma unroll
        for (int ch = 0; ch < 5; ch++) {
            float a = loc[ch];
#pragma unroll
            for (int o = 16; o; o >>= 1) a += __shfl_down_sync(0xffffffffu, a, o);
            if (lane == 0) red[wid] = a;
            __syncthreads();
            if (tid == 0) {
                float t = 0.f;
#pragma unroll
                for (int k = 0; k < 32; k++) t += red[k];
                sHdc[ch] = t;
            }
            __syncthreads();
        }

        // ---- time encoding (thread 0) ----
        if (tid == 0) {
            float tin  = t_in_arr[0]  * 0.01f;
            float tout = t_out_arr[0] * 0.01f;
            float pe[MODES];
#pragma unroll
            for (int i = 0; i < MODES; i++) {
                float div  = powf(10000.0f, 2.0f * (float)(i / 2) / (float)MODES);
                pe[i] = (i % 2 == 0) ? 0.5f * (sinf(tin / div) + cosf(tin / div))
                                     : 0.5f * (cosf(tin / div) + sinf(tout / div));
            }
#pragma unroll
            for (int r = 0; r < 5; r++) {
                float a = ctb[r];
#pragma unroll
                for (int m = 0; m < MODES; m++) a += pe[m] * ctw[r * MODES + m];
                ste[r] = tanhf(a);
            }
        }
        __syncthreads();

        // ---- dataSum[p] = sum_c data0[c,h,w] * (1 + te[c]) ----
        for (int p = tid; p < HW; p += 1024) {
            int h = p / S, w = p % S;
            float acc = 0.f;
#pragma unroll
            for (int c = 0; c < 4; c++)
                acc += din[(size_t)(c * S + h) * S + w] * (1.0f + ste[c]);
            acc += sin_in[p] * (1.0f + ste[4]);
            sDS[p] = acc;
        }
    }
    __syncthreads();

    const float csum = c3[0] + c3[1] + c3[2] + c3[3] + c3[4];

    // x = tanh( sum_r c3[r]*(mp2 - 2*proj*mp + proj^2) + c3b ) into padded hA
    for (int i = tid; i < 5 * HW; i += 1024) {
        int d = i / HW, p = i - d * HW;
        int h = p / S,  w = p - h * S;
        float a = 0.f, bm = 0.f;
#pragma unroll
        for (int r = 0; r < 5; r++) {
            int ri = (r * 5 + d) * HW + p;
            a  += c3[r] * g_mp2[ri];
            bm += c3[r] * g_mp [ri];
        }
        float proj = gen ? 0.f : (sHdc[d] * sDS[p]);
        hA[d * PHW + (h + 1) * PS + (w + 1)] =
            fast_tanh(a - 2.f * proj * bm + proj * proj * csum + c3bS);
    }
    __syncthreads();

    // ---- 8-step NCA: warp-per-(channel, 4-row strip) conv -----------------
    // task t = c*8 + q : output data rows [4q, 4q+3] of channel c.
    float* cur = hA;
    float* nxt = hB;
    for (int st = 0; st < STEPS; st++) {
        float ps = sp[st];
        for (int t = wid; t < 40; t += 32) {
            int c  = t >> 3;
            int r0 = (t & 7) * 4;
            if (lane < S) {
                float acc[4];
#pragma unroll
                for (int j = 0; j < 4; j++) acc[j] = bb[c];

#pragma unroll
                for (int ci = 0; ci < 5; ci++) {
                    const float* base = cur + ci * PHW;
                    const float* wrp  = w9 + (c * 5 + ci) * 9;
                    float wv[9];
#pragma unroll
                    for (int k = 0; k < 9; k++) wv[k] = wrp[k];

#pragma unroll
                    for (int ir = 0; ir < 6; ir++) {
                        int pr = r0 + ir;                // padded input row
                        float xl = 0.f, xc = 0.f, xr = 0.f;
                        if (pr < PS) {
                            const float* rp = base + pr * PS + lane;
                            xl = rp[0]; xc = rp[1]; xr = rp[2];
                        }
#pragma unroll
                        for (int j = 0; j < 4; j++) {
                            int kr = ir - j;             // kernel row
                            if (kr < 0 || kr > 2) continue;
                            acc[j] += wv[kr*3+0]*xl + wv[kr*3+1]*xc + wv[kr*3+2]*xr;
                        }
                    }
                }
#pragma unroll
                for (int j = 0; j < 4; j++) {
                    int orow = r0 + j;
                    if (orow < S) {
                        int pos = c * PHW + (orow + 1) * PS + (lane + 1);
                        nxt[pos] = cur[pos] + fast_tanh(acc[j]) * ps;
                    }
                }
            }
        }
        __syncthreads();
        float* tmp = cur; cur = nxt; nxt = tmp;
    }

    // out conv: (5->5) 1x1
    float* dst = gen ? g_outg : g_out0;
    for (int i = tid; i < 5 * HW; i += 1024) {
        int o = i / HW, p = i - o * HW;
        int h = p / S,  w = p - h * S;
        int pp = (h + 1) * PS + (w + 1);
        float v0 = cur[0*PHW + pp], v1 = cur[1*PHW + pp], v2 = cur[2*PHW + pp],
              v3 = cur[3*PHW + pp], v4 = cur[4*PHW + pp];
        dst[i] = ob[o] + ow[o*5+0]*v0 + ow[o*5+1]*v1 + ow[o*5+2]*v2
                       + ow[o*5+3]*v3 + ow[o*5+4]*v4;
    }
}

// ====== Kernel C: broadcast — one block per (o,b) slice, coalesced =========
__global__ __launch_bounds__(256)
void writeout_kernel(float* __restrict__ out)
{
    const int s = blockIdx.x;          // s = o*B + b
    const int b = s & (B - 1);
    const int o = s >> 8;              // B == 256
    const float* __restrict__ src = ((b == 0) ? g_out0 : g_outg) + o * HW;
    float* __restrict__ dst = out + (size_t)s * HW;
#pragma unroll
    for (int k = 0; k < 4; k++) {
        int p = threadIdx.x + k * 256;
        if (p < HW) dst[p] = src[p];
    }
}

// =================================== launch ================================
extern "C" void kernel_launch(void* const* d_in, const int* in_sizes, int n_in,
                              void* d_out, int out_size)
{
    const float* data_input  = (const float*)d_in[0];
    const float* structure   = (const float*)d_in[1];
    const float* meta_in     = (const float*)d_in[2];
    const float* meta_out    = (const float*)d_in[3];
    const float* spiking     = (const float*)d_in[4];
    const int*   nz_indices  = (const int*)  d_in[5];
    const int*   signs_raw   = (const int*)  d_in[6];
    const float* rbf_probes  = (const float*)d_in[7];
    const float* ct_w        = (const float*)d_in[8];
    const float* ct_b        = (const float*)d_in[9];
    const float* c3_w        = (const float*)d_in[10];
    const float* c3_b        = (const float*)d_in[11];
    const float* nca_w       = (const float*)d_in[12];
    const float* nca_b       = (const float*)d_in[13];
    const float* out_w       = (const float*)d_in[14];
    const float* out_b       = (const float*)d_in[15];
    float* out = (float*)d_out;

    const int nnz = in_sizes[5];
    const int nblk = ROWBLK + (nnz + 255) / 256;

    probe_scatter_kernel<<<nblk, 256>>>(rbf_probes, nz_indices, signs_raw, nnz);

    nca_kernel<<<2, 1024>>>(data_input, structure, meta_in, meta_out,
                            ct_w, ct_b, c3_w, c3_b, nca_w, nca_b,
                            spiking, out_w, out_b);

    writeout_kernel<<<5 * B, 256>>>(out);
}

// round 6
// speedup vs baseline: 1.6416x; 1.0917x over previous
#include <cuda_runtime.h>
#include <math.h>

// ---------------- problem constants ----------------
#define S      31
#define HW     (S*S)          // 961
#define B      256
#define HDC    4096
#define RBF    5
#define MODES  16
#define STEPS  8
#define NROWS  (RBF*5*HW)     // 24025 reduction rows of 4096 floats
#define NSLOTS (5*HDC)        // 20480 scatter slots (batch 0 only)
#define ROWBLK ((NROWS*32 + 255)/256)   // blocks doing row reductions (warp/row)

// padded NCA tile: 33x33 per channel (zero border)
#define PS  33
#define PHW (PS*PS)           // 1089
#define NCATHREADS 768        // 24 warps -> 85-reg budget

// ---------------- device scratch (no allocation; zero-initialized) --------
__device__ float g_mp [NROWS];
__device__ float g_mp2[NROWS];
__device__ int   g_pack[NSLOTS];   // 0 = empty; else ((i+1)<<1)|sign
__device__ float g_out0[5*HW];
__device__ float g_outg[5*HW];

__device__ __forceinline__ float fast_tanh(float x)
{
    float cx = fminf(fmaxf(x, -15.f), 15.f);
    float e  = __expf(2.f * cx);
    return __fdividef(e - 1.f, e + 1.f);
}

// ====== Kernel A: probe mean/mean-sq (warp per row) + fused scatter =======
__global__ __launch_bounds__(256)
void probe_scatter_kernel(const float* __restrict__ probes,
                          const int*   __restrict__ nzi,
                          const int*   __restrict__ signs, int nnz)
{
    if (blockIdx.x >= ROWBLK) {
        int i = (blockIdx.x - ROWBLK) * 256 + threadIdx.x;
        if (i < nnz) {
            int slot = nzi[i];
            if (slot >= 0 && slot < NSLOTS) {
                int packed = ((i + 1) << 1) | (signs[i] & 1);
                atomicMax(&g_pack[slot], packed);
            }
        }
        return;
    }

    const int gwarp = (blockIdx.x * 256 + threadIdx.x) >> 5;
    const int lane  = threadIdx.x & 31;
    if (gwarp >= NROWS) return;

    const float4* __restrict__ p =
        reinterpret_cast<const float4*>(probes) + (size_t)gwarp * 1024;

    float s = 0.f, s2 = 0.f;
#pragma unroll
    for (int i = 0; i < 32; i++) {
        float4 v = p[lane + i * 32];
        s  += (v.x + v.y) + (v.z + v.w);
        s2 += (v.x*v.x + v.y*v.y) + (v.z*v.z + v.w*v.w);
    }
#pragma unroll
    for (int o = 16; o; o >>= 1) {
        s  += __shfl_down_sync(0xffffffffu, s,  o);
        s2 += __shfl_down_sync(0xffffffffu, s2, o);
    }
    if (lane == 0) {
        g_mp [gwarp] = s  * (1.f / 4096.f);
        g_mp2[gwarp] = s2 * (1.f / 4096.f);
    }
}

// ====== Kernel B: chansum + te + RBF + 8-step NCA + out conv ==============
// grid = 4: blockIdx.x = state*2 + half
//   state 0: batch-0 (does chansum/te/dataSum prep, non-destructive)
//   state 1: generic (proj = 0)
//   half 0: owns output rows 0..15,  conv window rows 0..23
//   half 1: owns output rows 16..30, conv window rows 7..30
__global__ __launch_bounds__(NCATHREADS, 1)
void nca_kernel(const float* __restrict__ din,      // (B,124,31), batch 0
                const float* __restrict__ sin_in,   // (B,31,31),  batch 0
                const float* __restrict__ t_in_arr,
                const float* __restrict__ t_out_arr,
                const float* __restrict__ ctw,      // (5,16)
                const float* __restrict__ ctb,      // (5,)
                const float* __restrict__ c3w,      // (5,)
                const float* __restrict__ c3b,      // scalar
                const float* __restrict__ ncaw,     // (5,5,3,3)
                const float* __restrict__ ncab,     // (5,)
                const float* __restrict__ spike,    // (8,)
                const float* __restrict__ outw,     // (5,5)
                const float* __restrict__ outb)     // (5,)
{
    __shared__ float hA[5 * PHW];
    __shared__ float hB[5 * PHW];
    __shared__ float sDS[HW];
    __shared__ float w9[225], bb[5], sp[8], ow[25], ob[5], c3[5];
    __shared__ float sHdc[5];
    __shared__ float ste[5];
    __shared__ float c3bS;
    __shared__ float red[NCATHREADS/32];

    const int  tid  = threadIdx.x;            // 768
    const int  lane = tid & 31, wid = tid >> 5;
    const bool gen  = (blockIdx.x >= 2);
    const int  half = blockIdx.x & 1;
    const int  woff = half ? 7 : 0;            // conv window base row

    if (tid < 225) w9[tid] = ncaw[tid];
    if (tid < 25)  ow[tid] = outw[tid];
    if (tid < 8)   sp[tid] = spike[tid];
    if (tid < 5) { bb[tid] = ncab[tid]; ob[tid] = outb[tid]; c3[tid] = c3w[tid]; }
    if (tid == 0) c3bS = c3b[0];

    // zero both padded tiles (borders & outside-window rows must be 0)
    for (int i = tid; i < 5 * PHW; i += NCATHREADS) { hA[i] = 0.f; hB[i] = 0.f; }

    if (!gen) {
        // ---- per-channel sign sums from packed scatter (NON-destructive) --
        float loc[5] = {0.f, 0.f, 0.f, 0.f, 0.f};
#pragma unroll
        for (int ch = 0; ch < 5; ch++) {
            for (int sl = ch * HDC + tid; sl < (ch + 1) * HDC; sl += NCATHREADS) {
                int v = g_pack[sl];
                if (v) loc[ch] += (float)((v & 1) * 2 - 1);
            }
        }
#pragma unroll
        for (int ch = 0; ch < 5; ch++) {
            float a = loc[ch];
#pragma unroll
            for (int o = 16; o; o >>= 1) a += __shfl_down_sync(0xffffffffu, a, o);
            if (lane == 0) red[wid] = a;
            __syncthreads();
            if (tid == 0) {
                float t = 0.f;
#pragma unroll
                for (int k = 0; k < NCATHREADS/32; k++) t += red[k];
                sHdc[ch] = t;
            }
            __syncthreads();
        }

        // ---- time encoding (thread 0) ----
        if (tid == 0) {
            float tin  = t_in_arr[0]  * 0.01f;
            float tout = t_out_arr[0] * 0.01f;
            float pe[MODES];
#pragma unroll
            for (int i = 0; i < MODES; i++) {
                float div  = powf(10000.0f, 2.0f * (float)(i / 2) / (float)MODES);
                pe[i] = (i % 2 == 0) ? 0.5f * (sinf(tin / div) + cosf(tin / div))
                                     : 0.5f * (cosf(tin / div) + sinf(tout / div));
            }
#pragma unroll
            for (int r = 0; r < 5; r++) {
                float a = ctb[r];
#pragma unroll
                for (int m = 0; m < MODES; m++) a += pe[m] * ctw[r * MODES + m];
                ste[r] = tanhf(a);
            }
        }
        __syncthreads();

        // ---- dataSum[p] = sum_c data0[c,h,w] * (1 + te[c]) ----
        for (int p = tid; p < HW; p += NCATHREADS) {
            int h = p / S, w = p % S;
            float acc = 0.f;
#pragma unroll
            for (int c = 0; c < 4; c++)
                acc += din[(size_t)(c * S + h) * S + w] * (1.0f + ste[c]);
            acc += sin_in[p] * (1.0f + ste[4]);
            sDS[p] = acc;
        }
    }
    __syncthreads();

    const float csum = c3[0] + c3[1] + c3[2] + c3[3] + c3[4];

    // ---- RBF init: fill the 24-row window (5 ch x 24 rows x 31 cols) ------
    for (int i = tid; i < 5 * 24 * S; i += NCATHREADS) {
        int d  = i / (24 * S);
        int rm = i - d * (24 * S);
        int rr = rm / S, w = rm - rr * S;
        int h  = woff + rr;
        int p  = h * S + w;
        float a = 0.f, bm = 0.f;
#pragma unroll
        for (int r = 0; r < 5; r++) {
            int ri = (r * 5 + d) * HW + p;
            a  += c3[r] * g_mp2[ri];
            bm += c3[r] * g_mp [ri];
        }
        float proj = gen ? 0.f : (sHdc[d] * sDS[p]);
        hA[d * PHW + (h + 1) * PS + (w + 1)] =
            fast_tanh(a - 2.f * proj * bm + proj * proj * csum + c3bS);
    }
    __syncthreads();

    // ---- 8-step NCA conv: warp = (out-channel, 6-row strip) ---------------
    // 20 active warps; weights for this warp's out-channel held in registers
    // across all steps. Contamination creeps 1 row/step from the window edge;
    // after 8 steps the owned 15-16 rows are still clean.
    const int  c      = wid / 4;               // out channel (warps 0..19)
    const int  q      = wid & 3;               // strip index
    const int  rbase  = woff + q * 6;          // first output data row
    const bool active = (wid < 20) && (lane < S);

    float wv[45];
    if (wid < 20) {
#pragma unroll
        for (int k = 0; k < 45; k++) wv[k] = w9[c * 45 + k];
    }

    float* cur = hA;
    float* nxt = hB;
    for (int st = 0; st < STEPS; st++) {
        float ps = sp[st];
        if (active) {
            float acc[6];
#pragma unroll
            for (int j = 0; j < 6; j++) acc[j] = bb[c];

#pragma unroll
            for (int ci = 0; ci < 5; ci++) {
                const float* base = cur + ci * PHW;
#pragma unroll
                for (int ir = 0; ir < 8; ir++) {
                    // input data row = rbase-1+ir  ->  tile row = rbase+ir
                    const float* rp = base + (rbase + ir) * PS + lane;
                    float xl = rp[0], xc = rp[1], xr = rp[2];
#pragma unroll
                    for (int j = 0; j < 6; j++) {
                        int kr = ir - j;
                        if (kr < 0 || kr > 2) continue;
                        acc[j] += wv[ci*9 + kr*3 + 0] * xl
                                + wv[ci*9 + kr*3 + 1] * xc
                                + wv[ci*9 + kr*3 + 2] * xr;
                    }
                }
            }
#pragma unroll
            for (int j = 0; j < 6; j++) {
                int pos = c * PHW + (rbase + j + 1) * PS + (lane + 1);
                nxt[pos] = cur[pos] + fast_tanh(acc[j]) * ps;
            }
        }
        __syncthreads();
        float* tmp = cur; cur = nxt; nxt = tmp;
    }

    // ---- out conv (5->5, 1x1) over this block's OWNED rows ----------------
    const int rlo   = half ? 16 : 0;
    const int nrows = half ? 15 : 16;
    float* dst = gen ? g_outg : g_out0;
    for (int i = tid; i < 5 * nrows * S; i += NCATHREADS) {
        int o  = i / (nrows * S);
        int rm = i - o * (nrows * S);
        int rr = rm / S, w = rm - rr * S;
        int h  = rlo + rr;
        int pp = (h + 1) * PS + (w + 1);
        float v0 = cur[0*PHW + pp], v1 = cur[1*PHW + pp], v2 = cur[2*PHW + pp],
              v3 = cur[3*PHW + pp], v4 = cur[4*PHW + pp];
        dst[o * HW + h * S + w] =
            ob[o] + ow[o*5+0]*v0 + ow[o*5+1]*v1 + ow[o*5+2]*v2
                  + ow[o*5+3]*v3 + ow[o*5+4]*v4;
    }
}

// ====== Kernel C: broadcast (one block per (o,b) slice) + g_pack reset =====
__global__ __launch_bounds__(256)
void writeout_kernel(float* __restrict__ out)
{
    if (blockIdx.x >= 5 * B) {
        // reset scatter array for next replay (runs after nca consumed it)
        int i = (blockIdx.x - 5 * B) * 256 + threadIdx.x;
        if (i < NSLOTS) g_pack[i] = 0;
        return;
    }
    const int s = blockIdx.x;          // s = o*B + b
    const int b = s & (B - 1);
    const int o = s >> 8;              // B == 256
    const float* __restrict__ src = ((b == 0) ? g_out0 : g_outg) + o * HW;
    float* __restrict__ dst = out + (size_t)s * HW;
#pragma unroll
    for (int k = 0; k < 4; k++) {
        int p = threadIdx.x + k * 256;
        if (p < HW) dst[p] = src[p];
    }
}

// =================================== launch ================================
extern "C" void kernel_launch(void* const* d_in, const int* in_sizes, int n_in,
                              void* d_out, int out_size)
{
    const float* data_input  = (const float*)d_in[0];
    const float* structure   = (const float*)d_in[1];
    const float* meta_in     = (const float*)d_in[2];
    const float* meta_out    = (const float*)d_in[3];
    const float* spiking     = (const float*)d_in[4];
    const int*   nz_indices  = (const int*)  d_in[5];
    const int*   signs_raw   = (const int*)  d_in[6];
    const float* rbf_probes  = (const float*)d_in[7];
    const float* ct_w        = (const float*)d_in[8];
    const float* ct_b        = (const float*)d_in[9];
    const float* c3_w        = (const float*)d_in[10];
    const float* c3_b        = (const float*)d_in[11];
    const float* nca_w       = (const float*)d_in[12];
    const float* nca_b       = (const float*)d_in[13];
    const float* out_w       = (const float*)d_in[14];
    const float* out_b       = (const float*)d_in[15];
    float* out = (float*)d_out;

    const int nnz = in_sizes[5];
    const int nblk = ROWBLK + (nnz + 255) / 256;

    probe_scatter_kernel<<<nblk, 256>>>(rbf_probes, nz_indices, signs_raw, nnz);

    nca_kernel<<<4, NCATHREADS>>>(data_input, structure, meta_in, meta_out,
                                  ct_w, ct_b, c3_w, c3_b, nca_w, nca_b,
                                  spiking, out_w, out_b);

    const int resetblk = (NSLOTS + 255) / 256;
    writeout_kernel<<<5 * B + resetblk, 256>>>(out);
}